// round 16
// baseline (speedup 1.0000x reference)
#include <cuda_runtime.h>
#include <cuda_bf16.h>
#include <cstdint>
#include <math.h>

#define MM   16          // B*T
#define NN   5000
#define DIN  64
#define EE   80000
#define HC   128
#define E2   (EE + NN)   // 85000 with self loops
#define ROWS (MM * NN)   // 80000

// ---------------- scratch (no allocations allowed) ----------------
// feature buffers are NODE-major: row = n*MM + m
__device__ float g_xl[ROWS * HC];   // 41 MB
__device__ float g_xr[ROWS * HC];
__device__ float g_h [ROWS * HC];   // layer-1 output (node-major)
__device__ int   g_cnt[NN];
__device__ float g_wsum[NN];
__device__ int   g_rowoff[NN + 1];
__device__ int   g_fill[NN];
__device__ float g_selfw[NN];
__device__ int2  g_epk[E2];         // {src, bitcast(weight)}
// pre-split weights: [K x 256] = [Wl | Wr] in bf16 hi/lo
__device__ __nv_bfloat16 g_W1hi[DIN * 256], g_W1lo[DIN * 256];
__device__ __nv_bfloat16 g_W2hi[HC * 256],  g_W2lo[HC * 256];

// ---------------- preprocessing ----------------
// fused: zero counters + pre-split both weight matrices
__global__ void k_pre(const float* __restrict__ Wl1, const float* __restrict__ Wr1,
                      const float* __restrict__ Wl2, const float* __restrict__ Wr2) {
    int i = blockIdx.x * blockDim.x + threadIdx.x;
    if (i < NN) { g_cnt[i] = 0; g_wsum[i] = 0.f; }
    if (i < DIN * 256) {
        int k = i >> 8, n = i & 255;
        float v = (n < 128) ? Wl1[(size_t)k * 128 + n] : Wr1[(size_t)k * 128 + (n - 128)];
        __nv_bfloat16 h = __float2bfloat16(v);
        g_W1hi[i] = h;
        g_W1lo[i] = __float2bfloat16(v - __bfloat162float(h));
    }
    if (i < HC * 256) {
        int k = i >> 8, n = i & 255;
        float v = (n < 128) ? Wl2[(size_t)k * 128 + n] : Wr2[(size_t)k * 128 + (n - 128)];
        __nv_bfloat16 h = __float2bfloat16(v);
        g_W2hi[i] = h;
        g_W2lo[i] = __float2bfloat16(v - __bfloat162float(h));
    }
}

__global__ void k_deg(const int* __restrict__ ei, const float* __restrict__ ew) {
    int e = blockIdx.x * blockDim.x + threadIdx.x;
    if (e < EE) {
        int d = ei[EE + e];
        atomicAdd(&g_cnt[d], 1);
        atomicAdd(&g_wsum[d], ew[e]);
    }
}

// one block, 1024 threads: exclusive scan of (deg+1), self-loop weights
__global__ void k_scan() {
    __shared__ int sums[1024];
    int tid = threadIdx.x;
    int base = tid * 5;
    int loc[5];
    int s = 0;
#pragma unroll
    for (int j = 0; j < 5; j++) {
        int i = base + j;
        int d = (i < NN) ? (g_cnt[i] + 1) : 0;   // +1 for self loop
        loc[j] = s;
        s += d;
    }
    sums[tid] = s;
    __syncthreads();
    for (int off = 1; off < 1024; off <<= 1) {
        int v = (tid >= off) ? sums[tid - off] : 0;
        __syncthreads();
        sums[tid] += v;
        __syncthreads();
    }
    int excl = (tid == 0) ? 0 : sums[tid - 1];
#pragma unroll
    for (int j = 0; j < 5; j++) {
        int i = base + j;
        if (i < NN) {
            int o = excl + loc[j];
            g_rowoff[i] = o;
            g_fill[i]   = o;
            int c = g_cnt[i];
            g_selfw[i] = (c > 0) ? (g_wsum[i] / (float)c) : 0.f;
        }
    }
    if (tid == 1023) g_rowoff[NN] = sums[1023];
}

__global__ void k_scatter(const int* __restrict__ ei, const float* __restrict__ ew) {
    int i = blockIdx.x * blockDim.x + threadIdx.x;
    if (i < EE) {
        int d = ei[EE + i];
        int p = atomicAdd(&g_fill[d], 1);
        g_epk[p] = make_int2(ei[i], __float_as_int(ew[i]));
    } else if (i < E2) {
        int n = i - EE;
        int p = atomicAdd(&g_fill[n], 1);
        g_epk[p] = make_int2(n, __float_as_int(g_selfw[n]));
    }
}

// ---------------- tensor-core helpers ----------------
__device__ __forceinline__ void ldsm4(unsigned* r, unsigned addr) {
    asm volatile("ldmatrix.sync.aligned.m8n8.x4.shared.b16 {%0,%1,%2,%3}, [%4];"
        : "=r"(r[0]), "=r"(r[1]), "=r"(r[2]), "=r"(r[3]) : "r"(addr));
}
__device__ __forceinline__ void ldsm4t(unsigned* r, unsigned addr) {
    asm volatile("ldmatrix.sync.aligned.m8n8.x4.trans.shared.b16 {%0,%1,%2,%3}, [%4];"
        : "=r"(r[0]), "=r"(r[1]), "=r"(r[2]), "=r"(r[3]) : "r"(addr));
}
__device__ __forceinline__ void mma_bf16(float* c, const unsigned* a, const unsigned* b) {
    asm volatile(
        "mma.sync.aligned.m16n8k16.row.col.f32.bf16.bf16.f32 "
        "{%0,%1,%2,%3}, {%4,%5,%6,%7}, {%8,%9}, {%0,%1,%2,%3};"
        : "+f"(c[0]), "+f"(c[1]), "+f"(c[2]), "+f"(c[3])
        : "r"(a[0]), "r"(a[1]), "r"(a[2]), "r"(a[3]), "r"(b[0]), "r"(b[1]));
}
__device__ __forceinline__ void bsplit(float x, __nv_bfloat16& h, __nv_bfloat16& l) {
    h = __float2bfloat16(x);
    l = __float2bfloat16(x - __bfloat162float(h));
}

// ---------------- packed f32x2 helpers (proven legal in this harness, R4) ----
typedef unsigned long long u64;
__device__ __forceinline__ u64 p_add(u64 a, u64 b) {
    u64 r; asm("add.rn.f32x2 %0, %1, %2;" : "=l"(r) : "l"(a), "l"(b)); return r;
}
__device__ __forceinline__ u64 p_mul(u64 a, u64 b) {
    u64 r; asm("mul.rn.f32x2 %0, %1, %2;" : "=l"(r) : "l"(a), "l"(b)); return r;
}
__device__ __forceinline__ u64 p_fma(u64 a, u64 b, u64 c) {
    u64 r; asm("fma.rn.f32x2 %0, %1, %2, %3;" : "=l"(r) : "l"(a), "l"(b), "l"(c)); return r;
}
__device__ __forceinline__ u64 p_splat(float x) {
    u64 r; asm("mov.b64 %0, {%1, %1};" : "=l"(r) : "f"(x)); return r;
}
#define PMASK 0x7FFFFFFF7FFFFFFFull

// ---------------- projections: [xl | xr] = A @ [Wl | Wr] ----------------
// Tensor-core GEMM, bf16 2-term split (3 MMAs: hh + hl + lh) ~= fp32 accuracy.
// B comes pre-split in bf16 (g_W*hi/lo): staging is pure 16B copies, no cvt.
// Block: 32 rows x 256 cols, 256 threads (8 warps). Warp: 16 rows x 64 cols.
// MAP==1: A rows are (m*NN+n) (raw x) -> output row n*MM+m. IN_H: read g_h.
#define ASTR 40
#define BSTR 264
template <int K, int MAP, int IN_H>
__global__ void __launch_bounds__(256) k_gemm(const float* __restrict__ Ain,
                                              const __nv_bfloat16* __restrict__ Whi,
                                              const __nv_bfloat16* __restrict__ Wlo) {
    __shared__ __nv_bfloat16 As_hi[32 * ASTR];
    __shared__ __nv_bfloat16 As_lo[32 * ASTR];
    __shared__ __nv_bfloat16 Bs_hi[32 * BSTR];
    __shared__ __nv_bfloat16 Bs_lo[32 * BSTR];

    const float* __restrict__ A = IN_H ? (const float*)g_h : Ain;

    const int tid  = threadIdx.x;
    const int lane = tid & 31;
    const int w    = tid >> 5;
    const int mt   = w & 1;        // m-tile: rows mt*16..+15 of the 32
    const int nq   = w >> 1;       // n-quarter: cols nq*64..+63 of the 256
    const int row0 = blockIdx.x * 32;

    const unsigned ah_base = (unsigned)__cvta_generic_to_shared(As_hi);
    const unsigned al_base = (unsigned)__cvta_generic_to_shared(As_lo);
    const unsigned bh_base = (unsigned)__cvta_generic_to_shared(Bs_hi);
    const unsigned bl_base = (unsigned)__cvta_generic_to_shared(Bs_lo);

    float acc[8][4];
#pragma unroll
    for (int j = 0; j < 8; j++)
#pragma unroll
        for (int q = 0; q < 4; q++) acc[j][q] = 0.f;

    // staging maps
    const int sar = tid >> 3;            // A row 0..31
    const int sak = (tid & 7) * 4;       // A k-offset
    const unsigned a_row = (unsigned)(mt * 16 + (lane & 15));
    const unsigned a_coladd = (unsigned)((lane >> 4) << 3);
    const int bk_row = (lane & 7) + ((lane >> 3) & 1) * 8;
    const int b_nadd = (lane >> 4) << 3;

    for (int kc = 0; kc < K; kc += 32) {
        // ---- stage A chunk 32x32, split hi/lo ----
        {
            float4 v = *(const float4*)&A[(size_t)(row0 + sar) * K + kc + sak];
            __nv_bfloat16 h0, l0, h1, l1, h2, l2, h3, l3;
            bsplit(v.x, h0, l0); bsplit(v.y, h1, l1);
            bsplit(v.z, h2, l2); bsplit(v.w, h3, l3);
            __nv_bfloat16* ph = &As_hi[sar * ASTR + sak];
            __nv_bfloat16* pl = &As_lo[sar * ASTR + sak];
            ph[0] = h0; ph[1] = h1; ph[2] = h2; ph[3] = h3;
            pl[0] = l0; pl[1] = l1; pl[2] = l2; pl[3] = l3;
        }
        // ---- stage B chunk 32 x 256: pure 16-byte copies of pre-split bf16 ----
#pragma unroll
        for (int i = 0; i < 8; i++) {
            int idx = tid + i * 256;     // 0..2047 uint4 slots
            int arr = idx >> 10;         // 0: hi, 1: lo
            int rem = idx & 1023;
            int k   = rem >> 5;          // 0..31
            int c8  = (rem & 31) * 8;    // 0..248
            const __nv_bfloat16* src = (arr ? Wlo : Whi) + (size_t)(kc + k) * 256 + c8;
            __nv_bfloat16* dst = (arr ? Bs_lo : Bs_hi) + k * BSTR + c8;
            *(uint4*)dst = *(const uint4*)src;
        }
        __syncthreads();

        // ---- compute: 2 k16 steps ----
#pragma unroll
        for (int kk = 0; kk < 32; kk += 16) {
            unsigned ah[4], al[4];
            unsigned aoff = (a_row * ASTR + (unsigned)kk + a_coladd) * 2u;
            ldsm4(ah, ah_base + aoff);
            ldsm4(al, al_base + aoff);

            unsigned bh[16], bl[16];
#pragma unroll
            for (int t2 = 0; t2 < 4; t2++) {
                unsigned boff = ((unsigned)((kk + bk_row) * BSTR + nq * 64 + t2 * 16 + b_nadd)) * 2u;
                ldsm4t(&bh[t2 * 4], bh_base + boff);
                ldsm4t(&bl[t2 * 4], bl_base + boff);
            }
#pragma unroll
            for (int j = 0; j < 8; j++) {
                const unsigned* bhj = &bh[(j >> 1) * 4 + (j & 1) * 2];
                const unsigned* blj = &bl[(j >> 1) * 4 + (j & 1) * 2];
                mma_bf16(acc[j], ah, bhj);   // hi*hi
                mma_bf16(acc[j], ah, blj);   // hi*lo
                mma_bf16(acc[j], al, bhj);   // lo*hi
            }
        }
        __syncthreads();
    }

    // ---- epilogue ----
    int lrow = mt * 16 + (lane >> 2);
    int lcol = 2 * (lane & 3);
#pragma unroll
    for (int half = 0; half < 2; half++) {
        int r = row0 + lrow + half * 8;
        int orow;
        if (MAP == 1) {
            int m = r / NN;
            int n = r - m * NN;
            orow  = n * MM + m;
        } else {
            orow = r;
        }
#pragma unroll
        for (int j = 0; j < 8; j++) {
            int c = nq * 64 + j * 8 + lcol;
            float* buf = (c < 128) ? g_xl : g_xr;
            int cc = (c < 128) ? c : c - 128;
            *(float2*)&buf[(size_t)orow * HC + cc] =
                make_float2(acc[j][half * 2], acc[j][half * 2 + 1]);
        }
    }
}

// ---------------- fused edge kernel: packed f32x2 math ----------------
// One block per dst (grid NN, 8 warps). Warp handles TWO m's (lanes 0-15 /
// 16-31); lane owns 8 channels = 4 f32x2 pairs. Shifted-exp softmax (edge 0
// peeled as shift). Leaky-ReLU as 0.6t + 0.4|t| (exact), |t| = 64-bit AND.
template <int LAYER2>
__global__ void __launch_bounds__(256) k_edge(const float* __restrict__ We,
                                              const float* __restrict__ att,
                                              const float* __restrict__ bias,
                                              float* __restrict__ out) {
    int warp = threadIdx.x >> 5;
    int lane = threadIdx.x & 31;
    int dst  = blockIdx.x;
    int m    = (warp << 1) | (lane >> 4);
    int ch   = (lane & 15) << 3;      // channel base, 8 channels per lane

    u64 xi2[4], we2[4], at2[4];
    {
        const float* p = &g_xr[(size_t)(dst * MM + m) * HC + ch];
        ulonglong2 a = *(const ulonglong2*)p;
        ulonglong2 b = *(const ulonglong2*)(p + 4);
        xi2[0] = a.x; xi2[1] = a.y; xi2[2] = b.x; xi2[3] = b.y;
        ulonglong2 c = *(const ulonglong2*)&We[ch];
        ulonglong2 d = *(const ulonglong2*)&We[ch + 4];
        we2[0] = c.x; we2[1] = c.y; we2[2] = d.x; we2[3] = d.y;
        ulonglong2 e = *(const ulonglong2*)&att[ch];
        ulonglong2 f = *(const ulonglong2*)&att[ch + 4];
        at2[0] = e.x; at2[1] = e.y; at2[2] = f.x; at2[3] = f.y;
    }
    const u64 C06 = p_splat(0.6f), C04 = p_splat(0.4f);

    int beg = g_rowoff[dst];
    int end = g_rowoff[dst + 1];   // end - beg >= 1 (self loop)

    // packed logit over this lane's 4 pairs (returns lane-partial sum)
    auto logit8 = [&](const u64* xj2, u64 wp) -> float {
        u64 p2 = 0ull;
#pragma unroll
        for (int i = 0; i < 4; i++) {
            u64 t  = p_fma(wp, we2[i], p_add(xi2[i], xj2[i]));
            u64 ab = t & PMASK;
            u64 r  = p_fma(C04, ab, p_mul(C06, t));
            p2 = p_fma(r, at2[i], p2);
        }
        return __uint_as_float((unsigned)p2) + __uint_as_float((unsigned)(p2 >> 32));
    };

    // ---- peel edge 0: defines the shift; contributes exp(0)=1 ----
    u64 acc2[4];
    float off, dn = 1.f;
    {
        int2 e0 = g_epk[beg];
        u64 wp = p_splat(__int_as_float(e0.y));
        const float* p0 = &g_xl[(size_t)(e0.x * MM + m) * HC + ch];
        ulonglong2 a = *(const ulonglong2*)p0;
        ulonglong2 b = *(const ulonglong2*)(p0 + 4);
        u64 xj2[4] = {a.x, a.y, b.x, b.y};
        float p = logit8(xj2, wp);
#pragma unroll
        for (int o2 = 1; o2 <= 4; o2 <<= 1)
            p += __shfl_xor_sync(0xffffffffu, p, o2);
        off = p;
#pragma unroll
        for (int i = 0; i < 4; i++) acc2[i] = xj2[i];
    }

    // ---- dual-unrolled main loop ----
    int j = beg + 1;
    for (; j + 1 < end; j += 2) {
        int2 eA = g_epk[j];
        int2 eB = g_epk[j + 1];
        u64 wpA = p_splat(__int_as_float(eA.y));
        u64 wpB = p_splat(__int_as_float(eB.y));
        const float* pA = &g_xl[(size_t)(eA.x * MM + m) * HC + ch];
        const float* pB = &g_xl[(size_t)(eB.x * MM + m) * HC + ch];
        ulonglong2 a0 = *(const ulonglong2*)pA;
        ulonglong2 a1 = *(const ulonglong2*)(pA + 4);
        ulonglong2 b0 = *(const ulonglong2*)pB;
        ulonglong2 b1 = *(const ulonglong2*)(pB + 4);
        u64 xjA2[4] = {a0.x, a0.y, a1.x, a1.y};
        u64 xjB2[4] = {b0.x, b0.y, b1.x, b1.y};

        float pAv = logit8(xjA2, wpA);
        float pBv = logit8(xjB2, wpB);
#pragma unroll
        for (int o2 = 1; o2 <= 4; o2 <<= 1) {
            pAv += __shfl_xor_sync(0xffffffffu, pAv, o2);
            pBv += __shfl_xor_sync(0xffffffffu, pBv, o2);
        }

        float eA_ = __expf(pAv - off);
        float eB_ = __expf(pBv - off);
        dn += eA_ + eB_;
        u64 epA = p_splat(eA_), epB = p_splat(eB_);
#pragma unroll
        for (int i = 0; i < 4; i++)
            acc2[i] = p_fma(epB, xjB2[i], p_fma(epA, xjA2[i], acc2[i]));
    }
    if (j < end) {
        int2 eA = g_epk[j];
        u64 wpA = p_splat(__int_as_float(eA.y));
        const float* pA = &g_xl[(size_t)(eA.x * MM + m) * HC + ch];
        ulonglong2 a0 = *(const ulonglong2*)pA;
        ulonglong2 a1 = *(const ulonglong2*)(pA + 4);
        u64 xjA2[4] = {a0.x, a0.y, a1.x, a1.y};
        float pAv = logit8(xjA2, wpA);
#pragma unroll
        for (int o2 = 1; o2 <= 4; o2 <<= 1)
            pAv += __shfl_xor_sync(0xffffffffu, pAv, o2);
        float eA_ = __expf(pAv - off);
        dn += eA_;
        u64 epA = p_splat(eA_);
#pragma unroll
        for (int i = 0; i < 4; i++)
            acc2[i] = p_fma(epA, xjA2[i], acc2[i]);
    }

    float inv = 1.f / dn;   // dn >= 1, EPS negligible
    float o[8];
#pragma unroll
    for (int i = 0; i < 4; i++) {
        float a0 = __uint_as_float((unsigned)acc2[i]);
        float a1 = __uint_as_float((unsigned)(acc2[i] >> 32));
        float v0 = fmaf(a0, inv, bias[ch + 2 * i]);
        float v1 = fmaf(a1, inv, bias[ch + 2 * i + 1]);
        o[2 * i]     = (v0 > 0.f) ? v0 : (__expf(v0) - 1.f);   // ELU
        o[2 * i + 1] = (v1 > 0.f) ? v1 : (__expf(v1) - 1.f);
    }

    float* dstp = LAYER2 ? &out[(size_t)(m * NN + dst) * HC + ch]
                         : &g_h[(size_t)(dst * MM + m) * HC + ch];
    *(float4*)dstp       = *(float4*)&o[0];
    *(float4*)(dstp + 4) = *(float4*)&o[4];
}

// ---------------- launch ----------------
extern "C" void kernel_launch(void* const* d_in, const int* in_sizes, int n_in,
                              void* d_out, int out_size) {
    const float* x    = (const float*)d_in[0];
    const int*   ei   = (const int*)d_in[1];
    const float* ew   = (const float*)d_in[2];
    const float* Wl1  = (const float*)d_in[3];
    const float* Wr1  = (const float*)d_in[4];
    const float* att1 = (const float*)d_in[5];
    const float* We1  = (const float*)d_in[6];
    const float* b1   = (const float*)d_in[7];
    const float* Wl2  = (const float*)d_in[8];
    const float* Wr2  = (const float*)d_in[9];
    const float* att2 = (const float*)d_in[10];
    const float* We2  = (const float*)d_in[11];
    const float* b2   = (const float*)d_in[12];
    float* out = (float*)d_out;

    __nv_bfloat16 *w1hi, *w1lo, *w2hi, *w2lo;
    cudaGetSymbolAddress((void**)&w1hi, g_W1hi);
    cudaGetSymbolAddress((void**)&w1lo, g_W1lo);
    cudaGetSymbolAddress((void**)&w2hi, g_W2hi);
    cudaGetSymbolAddress((void**)&w2lo, g_W2lo);

    k_pre<<<(HC * 256 + 255) / 256, 256>>>(Wl1, Wr1, Wl2, Wr2);
    k_deg<<<(EE + 255) / 256, 256>>>(ei, ew);
    k_scan<<<1, 1024>>>();
    k_scatter<<<(E2 + 255) / 256, 256>>>(ei, ew);

    // layer 1
    k_gemm<DIN, 1, 0><<<ROWS / 32, 256>>>(x, w1hi, w1lo);
    k_edge<0><<<NN, 256>>>(We1, att1, b1, nullptr);

    // layer 2
    k_gemm<HC, 0, 1><<<ROWS / 32, 256>>>(nullptr, w2hi, w2lo);
    k_edge<1><<<NN, 256>>>(We2, att2, b2, out);
}

// round 17
// speedup vs baseline: 1.0171x; 1.0171x over previous
#include <cuda_runtime.h>
#include <cuda_bf16.h>
#include <cuda_fp16.h>
#include <cstdint>
#include <math.h>

#define MM   16          // B*T
#define NN   5000
#define DIN  64
#define EE   80000
#define HC   128
#define E2   (EE + NN)   // 85000 with self loops
#define ROWS (MM * NN)   // 80000

// ---------------- scratch (no allocations allowed) ----------------
// feature buffers are NODE-major: row = n*MM + m
__device__ float g_xl[ROWS * HC];   // 41 MB
__device__ float g_xr[ROWS * HC];
__device__ float g_h [ROWS * HC];   // layer-1 output (node-major)
__device__ int   g_cnt[NN];
__device__ float g_wsum[NN];
__device__ int   g_rowoff[NN + 1];
__device__ int   g_fill[NN];
__device__ float g_selfw[NN];
__device__ int2  g_epk[E2];         // {src, bitcast(weight)}
// pre-converted weights: Wl in fp16 (single-term xl path),
// Wr in bf16 hi/lo (3-term xr path). All [K x 128].
__device__ __half        g_W1f16[DIN * 128];
__device__ __nv_bfloat16 g_W1hi[DIN * 128], g_W1lo[DIN * 128];
__device__ __half        g_W2f16[HC * 128];
__device__ __nv_bfloat16 g_W2hi[HC * 128],  g_W2lo[HC * 128];

// ---------------- preprocessing ----------------
// fused: zero counters + pre-convert both weight matrices
__global__ void k_pre(const float* __restrict__ Wl1, const float* __restrict__ Wr1,
                      const float* __restrict__ Wl2, const float* __restrict__ Wr2) {
    int i = blockIdx.x * blockDim.x + threadIdx.x;
    if (i < NN) { g_cnt[i] = 0; g_wsum[i] = 0.f; }
    if (i < DIN * 128) {
        float vl = Wl1[i];
        g_W1f16[i] = __float2half(vl);
        float vr = Wr1[i];
        __nv_bfloat16 h = __float2bfloat16(vr);
        g_W1hi[i] = h;
        g_W1lo[i] = __float2bfloat16(vr - __bfloat162float(h));
    }
    if (i < HC * 128) {
        float vl = Wl2[i];
        g_W2f16[i] = __float2half(vl);
        float vr = Wr2[i];
        __nv_bfloat16 h = __float2bfloat16(vr);
        g_W2hi[i] = h;
        g_W2lo[i] = __float2bfloat16(vr - __bfloat162float(h));
    }
}

__global__ void k_deg(const int* __restrict__ ei, const float* __restrict__ ew) {
    int e = blockIdx.x * blockDim.x + threadIdx.x;
    if (e < EE) {
        int d = ei[EE + e];
        atomicAdd(&g_cnt[d], 1);
        atomicAdd(&g_wsum[d], ew[e]);
    }
}

// one block, 1024 threads: exclusive scan of (deg+1), self-loop weights
__global__ void k_scan() {
    __shared__ int sums[1024];
    int tid = threadIdx.x;
    int base = tid * 5;
    int loc[5];
    int s = 0;
#pragma unroll
    for (int j = 0; j < 5; j++) {
        int i = base + j;
        int d = (i < NN) ? (g_cnt[i] + 1) : 0;   // +1 for self loop
        loc[j] = s;
        s += d;
    }
    sums[tid] = s;
    __syncthreads();
    for (int off = 1; off < 1024; off <<= 1) {
        int v = (tid >= off) ? sums[tid - off] : 0;
        __syncthreads();
        sums[tid] += v;
        __syncthreads();
    }
    int excl = (tid == 0) ? 0 : sums[tid - 1];
#pragma unroll
    for (int j = 0; j < 5; j++) {
        int i = base + j;
        if (i < NN) {
            int o = excl + loc[j];
            g_rowoff[i] = o;
            g_fill[i]   = o;
            int c = g_cnt[i];
            g_selfw[i] = (c > 0) ? (g_wsum[i] / (float)c) : 0.f;
        }
    }
    if (tid == 1023) g_rowoff[NN] = sums[1023];
}

__global__ void k_scatter(const int* __restrict__ ei, const float* __restrict__ ew) {
    int i = blockIdx.x * blockDim.x + threadIdx.x;
    if (i < EE) {
        int d = ei[EE + i];
        int p = atomicAdd(&g_fill[d], 1);
        g_epk[p] = make_int2(ei[i], __float_as_int(ew[i]));
    } else if (i < E2) {
        int n = i - EE;
        int p = atomicAdd(&g_fill[n], 1);
        g_epk[p] = make_int2(n, __float_as_int(g_selfw[n]));
    }
}

// ---------------- tensor-core helpers ----------------
__device__ __forceinline__ void ldsm4(unsigned* r, unsigned addr) {
    asm volatile("ldmatrix.sync.aligned.m8n8.x4.shared.b16 {%0,%1,%2,%3}, [%4];"
        : "=r"(r[0]), "=r"(r[1]), "=r"(r[2]), "=r"(r[3]) : "r"(addr));
}
__device__ __forceinline__ void ldsm4t(unsigned* r, unsigned addr) {
    asm volatile("ldmatrix.sync.aligned.m8n8.x4.trans.shared.b16 {%0,%1,%2,%3}, [%4];"
        : "=r"(r[0]), "=r"(r[1]), "=r"(r[2]), "=r"(r[3]) : "r"(addr));
}
__device__ __forceinline__ void mma_bf16(float* c, const unsigned* a, const unsigned* b) {
    asm volatile(
        "mma.sync.aligned.m16n8k16.row.col.f32.bf16.bf16.f32 "
        "{%0,%1,%2,%3}, {%4,%5,%6,%7}, {%8,%9}, {%0,%1,%2,%3};"
        : "+f"(c[0]), "+f"(c[1]), "+f"(c[2]), "+f"(c[3])
        : "r"(a[0]), "r"(a[1]), "r"(a[2]), "r"(a[3]), "r"(b[0]), "r"(b[1]));
}
__device__ __forceinline__ void mma_f16(float* c, const unsigned* a, const unsigned* b) {
    asm volatile(
        "mma.sync.aligned.m16n8k16.row.col.f32.f16.f16.f32 "
        "{%0,%1,%2,%3}, {%4,%5,%6,%7}, {%8,%9}, {%0,%1,%2,%3};"
        : "+f"(c[0]), "+f"(c[1]), "+f"(c[2]), "+f"(c[3])
        : "r"(a[0]), "r"(a[1]), "r"(a[2]), "r"(a[3]), "r"(b[0]), "r"(b[1]));
}
__device__ __forceinline__ void bsplit(float x, __nv_bfloat16& h, __nv_bfloat16& l) {
    h = __float2bfloat16(x);
    l = __float2bfloat16(x - __bfloat162float(h));
}
__device__ __forceinline__ float lrelu(float t) { return fmaxf(t, 0.2f * t); }

// ---------------- projections ----------------
// xl = A @ Wl : SINGLE fp16 MMA per k16 (error ~2^-11; R6-validated accuracy).
// xr = A @ Wr : bf16 2-term split, 3 MMAs (hh+hl+lh), ~fp32 accuracy.
// Block: 32 rows x 256 cols, 256 threads (8 warps). Warp: 16 rows x 64 cols.
// Warps nq<2 -> xl (fp16), nq>=2 -> xr (bf16 split). One of each per SMSP.
// MAP==1: A rows are (m*NN+n) (raw x) -> output row n*MM+m. IN_H: read g_h.
#define ASTR 40
#define BSTRH 136
template <int K, int MAP, int IN_H>
__global__ void __launch_bounds__(256) k_gemm(const float* __restrict__ Ain,
                                              const __half* __restrict__ Wf16,
                                              const __nv_bfloat16* __restrict__ Whi,
                                              const __nv_bfloat16* __restrict__ Wlo) {
    __shared__ __half        As_f16[32 * ASTR];
    __shared__ __nv_bfloat16 As_hi[32 * ASTR];
    __shared__ __nv_bfloat16 As_lo[32 * ASTR];
    __shared__ __half        Bs_f16[32 * BSTRH];
    __shared__ __nv_bfloat16 Bs_hi[32 * BSTRH];
    __shared__ __nv_bfloat16 Bs_lo[32 * BSTRH];

    const float* __restrict__ A = IN_H ? (const float*)g_h : Ain;

    const int tid  = threadIdx.x;
    const int lane = tid & 31;
    const int w    = tid >> 5;
    const int mt   = w & 1;        // m-tile: rows mt*16..+15 of the 32
    const int nq   = w >> 1;       // 0,1 -> xl halves; 2,3 -> xr halves
    const int row0 = blockIdx.x * 32;

    const unsigned af_base = (unsigned)__cvta_generic_to_shared(As_f16);
    const unsigned ah_base = (unsigned)__cvta_generic_to_shared(As_hi);
    const unsigned al_base = (unsigned)__cvta_generic_to_shared(As_lo);
    const unsigned bf_base = (unsigned)__cvta_generic_to_shared(Bs_f16);
    const unsigned bh_base = (unsigned)__cvta_generic_to_shared(Bs_hi);
    const unsigned bl_base = (unsigned)__cvta_generic_to_shared(Bs_lo);

    float acc[8][4];
#pragma unroll
    for (int j = 0; j < 8; j++)
#pragma unroll
        for (int q = 0; q < 4; q++) acc[j][q] = 0.f;

    // staging maps
    const int sar = tid >> 3;            // A row 0..31
    const int sak = (tid & 7) * 4;       // A k-offset
    const unsigned a_row = (unsigned)(mt * 16 + (lane & 15));
    const unsigned a_coladd = (unsigned)((lane >> 4) << 3);
    const int bk_row = (lane & 7) + ((lane >> 3) & 1) * 8;
    const int b_nadd = (lane >> 4) << 3;
    const int ncol = (nq & 1) * 64;      // column base within the 128-col half

    for (int kc = 0; kc < K; kc += 32) {
        // ---- stage A chunk 32x32: fp16 + bf16 hi/lo ----
        {
            float4 v = *(const float4*)&A[(size_t)(row0 + sar) * K + kc + sak];
            __half2* pf = (__half2*)&As_f16[sar * ASTR + sak];
            pf[0] = __floats2half2_rn(v.x, v.y);
            pf[1] = __floats2half2_rn(v.z, v.w);
            __nv_bfloat16 h0, l0, h1, l1, h2, l2, h3, l3;
            bsplit(v.x, h0, l0); bsplit(v.y, h1, l1);
            bsplit(v.z, h2, l2); bsplit(v.w, h3, l3);
            __nv_bfloat162* ph = (__nv_bfloat162*)&As_hi[sar * ASTR + sak];
            ph[0] = __nv_bfloat162(h0, h1); ph[1] = __nv_bfloat162(h2, h3);
            __nv_bfloat162* pl = (__nv_bfloat162*)&As_lo[sar * ASTR + sak];
            pl[0] = __nv_bfloat162(l0, l1); pl[1] = __nv_bfloat162(l2, l3);
        }
        // ---- stage B chunk 32 x 128 x 3 arrays: pure 16B copies ----
#pragma unroll
        for (int i = 0; i < 6; i++) {
            int idx = tid + i * 256;     // 0..1535 uint4 slots (512 per array)
            int arr = idx >> 9;          // 0: f16, 1: hi, 2: lo
            int rem = idx & 511;
            int k   = rem >> 4;          // 0..31
            int c8  = (rem & 15) * 8;    // 0..120
            const void* src;
            void* dst;
            if (arr == 0) { src = &Wf16[(size_t)(kc + k) * 128 + c8]; dst = &Bs_f16[k * BSTRH + c8]; }
            else if (arr == 1) { src = &Whi[(size_t)(kc + k) * 128 + c8]; dst = &Bs_hi[k * BSTRH + c8]; }
            else { src = &Wlo[(size_t)(kc + k) * 128 + c8]; dst = &Bs_lo[k * BSTRH + c8]; }
            *(uint4*)dst = *(const uint4*)src;
        }
        __syncthreads();

        // ---- compute: 2 k16 steps ----
#pragma unroll
        for (int kk = 0; kk < 32; kk += 16) {
            unsigned aoff = (a_row * ASTR + (unsigned)kk + a_coladd) * 2u;
            if (nq < 2) {
                // xl: single fp16 term
                unsigned af[4];
                ldsm4(af, af_base + aoff);
                unsigned bf[16];
#pragma unroll
                for (int t2 = 0; t2 < 4; t2++) {
                    unsigned boff = ((unsigned)((kk + bk_row) * BSTRH + ncol + t2 * 16 + b_nadd)) * 2u;
                    ldsm4t(&bf[t2 * 4], bf_base + boff);
                }
#pragma unroll
                for (int j = 0; j < 8; j++)
                    mma_f16(acc[j], af, &bf[(j >> 1) * 4 + (j & 1) * 2]);
            } else {
                // xr: bf16 3-term split
                unsigned ah[4], al[4];
                ldsm4(ah, ah_base + aoff);
                ldsm4(al, al_base + aoff);
                unsigned bh[16], bl[16];
#pragma unroll
                for (int t2 = 0; t2 < 4; t2++) {
                    unsigned boff = ((unsigned)((kk + bk_row) * BSTRH + ncol + t2 * 16 + b_nadd)) * 2u;
                    ldsm4t(&bh[t2 * 4], bh_base + boff);
                    ldsm4t(&bl[t2 * 4], bl_base + boff);
                }
#pragma unroll
                for (int j = 0; j < 8; j++) {
                    const unsigned* bhj = &bh[(j >> 1) * 4 + (j & 1) * 2];
                    const unsigned* blj = &bl[(j >> 1) * 4 + (j & 1) * 2];
                    mma_bf16(acc[j], ah, bhj);   // hi*hi
                    mma_bf16(acc[j], ah, blj);   // hi*lo
                    mma_bf16(acc[j], al, bhj);   // lo*hi
                }
            }
        }
        __syncthreads();
    }

    // ---- epilogue ----
    float* buf = (nq < 2) ? g_xl : g_xr;
    int lrow = mt * 16 + (lane >> 2);
    int lcol = 2 * (lane & 3);
#pragma unroll
    for (int half = 0; half < 2; half++) {
        int r = row0 + lrow + half * 8;
        int orow;
        if (MAP == 1) {
            int m = r / NN;
            int n = r - m * NN;
            orow  = n * MM + m;
        } else {
            orow = r;
        }
#pragma unroll
        for (int j = 0; j < 8; j++) {
            int cc = ncol + j * 8 + lcol;
            *(float2*)&buf[(size_t)orow * HC + cc] =
                make_float2(acc[j][half * 2], acc[j][half * 2 + 1]);
        }
    }
}

// ---------------- fused edge kernel: gather + shifted-exp softmax + aggregate ----------------
// One block per dst (grid NN, 8 warps). Each warp handles TWO m's:
// lanes 0-15 -> m = 2*warp, lanes 16-31 -> m = 2*warp+1.
// Each lane owns 8 contiguous channels; 3-step shuffle reduction.
// Softmax: peel edge 0 (self loop guarantees deg>=1), use its logit as the
// fixed shift; accumulate exp(p - p0) directly. Exact by shift-invariance.
template <int LAYER2>
__global__ void __launch_bounds__(256) k_edge(const float* __restrict__ We,
                                              const float* __restrict__ att,
                                              const float* __restrict__ bias,
                                              float* __restrict__ out) {
    int warp = threadIdx.x >> 5;
    int lane = threadIdx.x & 31;
    int dst  = blockIdx.x;
    int m    = (warp << 1) | (lane >> 4);
    int ch   = (lane & 15) << 3;      // channel base, 8 channels per lane

    float xi[8], we[8], at[8];
    {
        const float* p = &g_xr[(size_t)(dst * MM + m) * HC + ch];
        *(float4*)&xi[0] = *(const float4*)p;
        *(float4*)&xi[4] = *(const float4*)(p + 4);
        *(float4*)&we[0] = *(const float4*)&We[ch];
        *(float4*)&we[4] = *(const float4*)&We[ch + 4];
        *(float4*)&at[0] = *(const float4*)&att[ch];
        *(float4*)&at[4] = *(const float4*)&att[ch + 4];
    }

    int beg = g_rowoff[dst];
    int end = g_rowoff[dst + 1];   // end - beg >= 1 (self loop)

    // ---- peel edge 0: defines the shift; contributes exp(0)=1 ----
    float acc[8];
    float off, dn = 1.f;
    {
        int2 e0 = g_epk[beg];
        float w0 = __int_as_float(e0.y);
        const float* p0 = &g_xl[(size_t)(e0.x * MM + m) * HC + ch];
        float xj[8];
        *(float4*)&xj[0] = *(const float4*)p0;
        *(float4*)&xj[4] = *(const float4*)(p0 + 4);
        float p = 0.f;
#pragma unroll
        for (int i = 0; i < 8; i++) {
            p = fmaf(lrelu(fmaf(w0, we[i], xi[i] + xj[i])), at[i], p);
            acc[i] = xj[i];
        }
#pragma unroll
        for (int o2 = 1; o2 <= 4; o2 <<= 1)
            p += __shfl_xor_sync(0xffffffffu, p, o2);
        off = p;
    }

    // ---- dual-unrolled main loop ----
    int j = beg + 1;
    for (; j + 1 < end; j += 2) {
        int2 eA = g_epk[j];
        int2 eB = g_epk[j + 1];
        float wA = __int_as_float(eA.y);
        float wB = __int_as_float(eB.y);
        float xjA[8], xjB[8];
        {
            const float* pA = &g_xl[(size_t)(eA.x * MM + m) * HC + ch];
            const float* pB = &g_xl[(size_t)(eB.x * MM + m) * HC + ch];
            *(float4*)&xjA[0] = *(const float4*)pA;
            *(float4*)&xjA[4] = *(const float4*)(pA + 4);
            *(float4*)&xjB[0] = *(const float4*)pB;
            *(float4*)&xjB[4] = *(const float4*)(pB + 4);
        }

        float pA = 0.f, pB = 0.f;
#pragma unroll
        for (int i = 0; i < 8; i++) {
            pA = fmaf(lrelu(fmaf(wA, we[i], xi[i] + xjA[i])), at[i], pA);
            pB = fmaf(lrelu(fmaf(wB, we[i], xi[i] + xjB[i])), at[i], pB);
        }
#pragma unroll
        for (int o2 = 1; o2 <= 4; o2 <<= 1) {
            pA += __shfl_xor_sync(0xffffffffu, pA, o2);
            pB += __shfl_xor_sync(0xffffffffu, pB, o2);
        }

        float eA_ = __expf(pA - off);
        float eB_ = __expf(pB - off);
        dn += eA_ + eB_;
#pragma unroll
        for (int i = 0; i < 8; i++)
            acc[i] = fmaf(eB_, xjB[i], fmaf(eA_, xjA[i], acc[i]));
    }
    if (j < end) {
        int2 eA = g_epk[j];
        float wA = __int_as_float(eA.y);
        float xjA[8];
        const float* pAp = &g_xl[(size_t)(eA.x * MM + m) * HC + ch];
        *(float4*)&xjA[0] = *(const float4*)pAp;
        *(float4*)&xjA[4] = *(const float4*)(pAp + 4);
        float pA = 0.f;
#pragma unroll
        for (int i = 0; i < 8; i++)
            pA = fmaf(lrelu(fmaf(wA, we[i], xi[i] + xjA[i])), at[i], pA);
#pragma unroll
        for (int o2 = 1; o2 <= 4; o2 <<= 1)
            pA += __shfl_xor_sync(0xffffffffu, pA, o2);
        float eA_ = __expf(pA - off);
        dn += eA_;
#pragma unroll
        for (int i = 0; i < 8; i++)
            acc[i] = fmaf(eA_, xjA[i], acc[i]);
    }

    float inv = 1.f / dn;   // dn >= 1, EPS negligible
    float o[8];
#pragma unroll
    for (int i = 0; i < 8; i++) {
        float v = acc[i] * inv + bias[ch + i];
        o[i] = (v > 0.f) ? v : (__expf(v) - 1.f);   // ELU
    }

    float* dstp = LAYER2 ? &out[(size_t)(m * NN + dst) * HC + ch]
                         : &g_h[(size_t)(dst * MM + m) * HC + ch];
    *(float4*)dstp       = *(float4*)&o[0];
    *(float4*)(dstp + 4) = *(float4*)&o[4];
}

// ---------------- launch ----------------
extern "C" void kernel_launch(void* const* d_in, const int* in_sizes, int n_in,
                              void* d_out, int out_size) {
    const float* x    = (const float*)d_in[0];
    const int*   ei   = (const int*)d_in[1];
    const float* ew   = (const float*)d_in[2];
    const float* Wl1  = (const float*)d_in[3];
    const float* Wr1  = (const float*)d_in[4];
    const float* att1 = (const float*)d_in[5];
    const float* We1  = (const float*)d_in[6];
    const float* b1   = (const float*)d_in[7];
    const float* Wl2  = (const float*)d_in[8];
    const float* Wr2  = (const float*)d_in[9];
    const float* att2 = (const float*)d_in[10];
    const float* We2  = (const float*)d_in[11];
    const float* b2   = (const float*)d_in[12];
    float* out = (float*)d_out;

    __half *w1f, *w2f;
    __nv_bfloat16 *w1hi, *w1lo, *w2hi, *w2lo;
    cudaGetSymbolAddress((void**)&w1f, g_W1f16);
    cudaGetSymbolAddress((void**)&w1hi, g_W1hi);
    cudaGetSymbolAddress((void**)&w1lo, g_W1lo);
    cudaGetSymbolAddress((void**)&w2f, g_W2f16);
    cudaGetSymbolAddress((void**)&w2hi, g_W2hi);
    cudaGetSymbolAddress((void**)&w2lo, g_W2lo);

    k_pre<<<(HC * 128 + 255) / 256, 256>>>(Wl1, Wr1, Wl2, Wr2);
    k_deg<<<(EE + 255) / 256, 256>>>(ei, ew);
    k_scan<<<1, 1024>>>();
    k_scatter<<<(E2 + 255) / 256, 256>>>(ei, ew);

    // layer 1
    k_gemm<DIN, 1, 0><<<ROWS / 32, 256>>>(x, w1f, w1hi, w1lo);
    k_edge<0><<<NN, 256>>>(We1, att1, b1, nullptr);

    // layer 2
    k_gemm<HC, 0, 1><<<ROWS / 32, 256>>>(nullptr, w2f, w2hi, w2lo);
    k_edge<1><<<NN, 256>>>(We2, att2, b2, out);
}